// round 2
// baseline (speedup 1.0000x reference)
#include <cuda_runtime.h>

// Problem constants (from reference)
#define BATCH   1024
#define NK      33          // ykinput rows = 33; also nonzero support width (2*16+1)
#define COLBASE 4080        // VECCNTR - 1 - 15 = 4096 - 16
#define VEC     8192
#define EPSF    0.01f

#define NBLOCKS 256         // 256 blocks * 4 warps = 1024 warps = BATCH rows
#define NTHREADS 128

__device__ float        g_rowsum[BATCH];
__device__ unsigned int g_count = 0;

__global__ void __launch_bounds__(NTHREADS)
ngl_kernel(const float* __restrict__ input,
           const float* __restrict__ output,
           const float* __restrict__ ykinput,
           float* __restrict__ out)
{
    __shared__ float yk_s[NK * NK];   // yk_s[k*33 + j] = ykinput[k, 4080+j]
    __shared__ float red_s[4];
    __shared__ int   s_last;

    const int tid = threadIdx.x;

    // ---- Load the only 33x33 slice of ykinput that can ever be touched ----
    #pragma unroll
    for (int i = tid; i < NK * NK; i += NTHREADS) {
        int k = i / NK;
        int j = i - k * NK;
        yk_s[i] = ykinput[k * VEC + COLBASE + j];
    }
    __syncthreads();

    const int warp = tid >> 5;
    const int lane = tid & 31;
    const int row  = blockIdx.x * 4 + warp;   // one warp per batch row

    // ---- Per-row parameters (uniform across the warp) ----
    const float4 in4 = *reinterpret_cast<const float4*>(input + row * 4);
    const float p0 = in4.x, p1 = in4.y, p2 = in4.z;
    const int   m  = (int)in4.w;              // 1..16, exact in fp32
    const float o0 = output[row * 3 + 0];
    const float o1 = output[row * 3 + 1];
    const float o2 = output[row * 3 + 2];

    // ---- (m-1)-fold 3-tap convolution on a 33-wide register array ----
    // a[idx] holds phmz column (COLBASE + idx - 1); halo a[0], a[34] stay 0.
    float a[NK + 2];
    #pragma unroll
    for (int i = 0; i < NK + 2; ++i) a[i] = 0.0f;
    a[16] = p0;   // col 4095
    a[17] = p1;   // col 4096
    a[18] = p2;   // col 4097

    for (int t = 0; t < m - 1; ++t) {
        float prev = 0.0f;                    // a[0] == 0 always
        #pragma unroll
        for (int j = 1; j <= NK; ++j) {
            float cur = a[j];
            a[j] = fmaf(p0, prev, fmaf(p1, cur, p2 * a[j + 1]));
            prev = cur;
        }
    }

    // ---- Lane-parallel over k: phim_y, psi_y, rational loss term ----
    float lsum = 0.0f;
    for (int k = lane; k < NK; k += 32) {     // lane 0 also does k=32
        const float* y = &yk_s[k * NK];       // stride 33 across lanes: conflict-free
        float p = 0.0f;
        #pragma unroll
        for (int j = 0; j < NK; ++j)
            p = fmaf(a[j + 1], y[j], p);
        const float psi = fmaf(o0, y[15], fmaf(o1, y[16], o2 * y[17]));
        const float d = p - psi;
        const float q = 1.0f - p;
        lsum += __fdividef(d * d, fmaf(q, q, EPSF));
    }

    // ---- Deterministic warp reduction, one value per row ----
    #pragma unroll
    for (int off = 16; off; off >>= 1)
        lsum += __shfl_down_sync(0xffffffffu, lsum, off);
    if (lane == 0)
        g_rowsum[row] = lsum;

    // ---- Last-block-done final reduction (single kernel, no 2nd launch) ----
    __syncthreads();
    if (tid == 0) {
        __threadfence();
        unsigned int old = atomicAdd(&g_count, 1u);
        s_last = (old == (unsigned int)(gridDim.x - 1));
    }
    __syncthreads();

    if (s_last) {
        float s = 0.0f;
        #pragma unroll
        for (int i = tid; i < BATCH; i += NTHREADS)
            s += __ldcg(&g_rowsum[i]);        // fixed order -> deterministic
        #pragma unroll
        for (int off = 16; off; off >>= 1)
            s += __shfl_down_sync(0xffffffffu, s, off);
        if (lane == 0)
            red_s[warp] = s;
        __syncthreads();
        if (tid == 0) {
            *out = red_s[0] + red_s[1] + red_s[2] + red_s[3];
            g_count = 0;                      // re-arm for next graph replay
        }
    }
}

extern "C" void kernel_launch(void* const* d_in, const int* in_sizes, int n_in,
                              void* d_out, int out_size)
{
    const float* input   = (const float*)d_in[0];   // (1024, 4)
    const float* output  = (const float*)d_in[1];   // (1024, 3)
    const float* ykinput = (const float*)d_in[2];   // (33, 8192)
    float* out = (float*)d_out;                     // scalar loss
    (void)in_sizes; (void)n_in; (void)out_size;

    ngl_kernel<<<NBLOCKS, NTHREADS>>>(input, output, ykinput, out);
}

// round 3
// speedup vs baseline: 1.0037x; 1.0037x over previous
#include <cuda_runtime.h>

// Problem constants (from reference)
#define BATCH   1024
#define NK      33          // ykinput rows = 33; nonzero support width (2*16+1)
#define COLBASE 4080        // VECCNTR - 1 - 15
#define VEC     8192
#define EPSF    0.01f

#define NBLOCKS 128         // one wave: 128 blocks <= 148 SMs
#define NTHREADS 256        // 8 warps per block, one warp per batch row
#define WPB     8

__device__ float        g_blocksum[NBLOCKS];
__device__ unsigned int g_count = 0;

__global__ void __launch_bounds__(NTHREADS)
ngl_kernel(const float* __restrict__ input,
           const float* __restrict__ output,
           const float* __restrict__ ykinput,
           float* __restrict__ out)
{
    __shared__ float yk_s[NK * NK];     // yk_s[k*33 + j] = ykinput[k, 4080+j]
    __shared__ float a_s[WPB][64];      // per-warp coefficient exchange
    __shared__ float wsum_s[WPB];
    __shared__ int   s_last;

    const int tid  = threadIdx.x;
    const int warp = tid >> 5;
    const int lane = tid & 31;
    const int row  = blockIdx.x * WPB + warp;   // one warp per batch row

    // ---- Issue per-row parameter loads first (overlap with tile load) ----
    const float4 in4 = *reinterpret_cast<const float4*>(input + row * 4);
    const float p0 = in4.x, p1 = in4.y, p2 = in4.z;
    const int   m  = (int)in4.w;                // 1..16, exact in fp32
    const float o0 = output[row * 3 + 0];
    const float o1 = output[row * 3 + 1];
    const float o2 = output[row * 3 + 2];

    // ---- Load the only 33x33 slice of ykinput that can ever be touched ----
    for (int i = tid; i < NK * NK; i += NTHREADS) {
        int k = i / NK;
        int j = i - k * NK;
        yk_s[i] = ykinput[k * VEC + COLBASE + j];
    }

    // ---- Lane-distributed (m-1)-fold 3-tap convolution ----
    // c[j] = value at column COLBASE+j. Lane l owns e=c[2l], o=c[2l+1].
    // Support after t steps is [15-t, 17+t] (max [0,32]); 64-slot window exact.
    float e = 0.0f, o = 0.0f;
    if (lane == 7) { o = p0; }               // c[15]
    if (lane == 8) { e = p1; o = p2; }       // c[16], c[17]

    for (int t = 0; t < m - 1; ++t) {
        float o_up = __shfl_up_sync(0xffffffffu, o, 1);   // c[2l-1]
        float e_dn = __shfl_down_sync(0xffffffffu, e, 1); // c[2l+2]
        if (lane == 0)  o_up = 0.0f;
        if (lane == 31) e_dn = 0.0f;
        float e_new = fmaf(p0, o_up, fmaf(p1, e, p2 * o));
        float o_new = fmaf(p0, e,    fmaf(p1, o, p2 * e_dn));
        e = e_new;
        o = o_new;
    }

    a_s[warp][2 * lane]     = e;
    a_s[warp][2 * lane + 1] = o;
    __syncthreads();    // covers yk_s fill AND per-warp coefficient exchange

    // ---- Hoist coefficients into registers (broadcast LDS, conflict-free) --
    float areg[NK];
    #pragma unroll
    for (int j = 0; j < NK; ++j) areg[j] = a_s[warp][j];

    // ---- Lane-parallel over k: phim_y, psi_y, rational loss term ----
    float lsum = 0.0f;
    for (int k = lane; k < NK; k += 32) {     // lane 0 also does k=32
        const float* y = &yk_s[k * NK];       // stride 33 across lanes: conflict-free
        float p = 0.0f;
        #pragma unroll
        for (int j = 0; j < NK; ++j)
            p = fmaf(areg[j], y[j], p);
        const float psi = fmaf(o0, y[15], fmaf(o1, y[16], o2 * y[17]));
        const float d = p - psi;
        const float q = 1.0f - p;
        lsum += __fdividef(d * d, fmaf(q, q, EPSF));
    }

    // ---- Deterministic warp reduction ----
    #pragma unroll
    for (int off = 16; off; off >>= 1)
        lsum += __shfl_down_sync(0xffffffffu, lsum, off);
    if (lane == 0)
        wsum_s[warp] = lsum;
    __syncthreads();

    // ---- Block sum (fixed order), then last-block-done final reduction ----
    if (tid == 0) {
        float bs = 0.0f;
        #pragma unroll
        for (int w = 0; w < WPB; ++w) bs += wsum_s[w];
        g_blocksum[blockIdx.x] = bs;
        __threadfence();
        unsigned int old = atomicAdd(&g_count, 1u);
        s_last = (old == (unsigned int)(NBLOCKS - 1));
    }
    __syncthreads();

    if (s_last) {
        float s = (tid < NBLOCKS) ? __ldcg(&g_blocksum[tid]) : 0.0f;
        #pragma unroll
        for (int off = 16; off; off >>= 1)
            s += __shfl_down_sync(0xffffffffu, s, off);
        if (lane == 0)
            wsum_s[warp] = s;
        __syncthreads();
        if (tid == 0) {
            float r = 0.0f;
            #pragma unroll
            for (int w = 0; w < WPB; ++w) r += wsum_s[w];
            *out = r;
            g_count = 0;                      // re-arm for next graph replay
        }
    }
}

extern "C" void kernel_launch(void* const* d_in, const int* in_sizes, int n_in,
                              void* d_out, int out_size)
{
    const float* input   = (const float*)d_in[0];   // (1024, 4)
    const float* output  = (const float*)d_in[1];   // (1024, 3)
    const float* ykinput = (const float*)d_in[2];   // (33, 8192)
    float* out = (float*)d_out;                     // scalar loss
    (void)in_sizes; (void)n_in; (void)out_size;

    ngl_kernel<<<NBLOCKS, NTHREADS>>>(input, output, ykinput, out);
}